// round 10
// baseline (speedup 1.0000x reference)
#include <cuda_runtime.h>
#include <cuda_bf16.h>
#include <math.h>
#include <stdint.h>

#define TT    19
#define INLEN 10
#define GPX   8192
#define LS    (GPX*64)
typedef __nv_bfloat16 bf;

// ---------------- device scratch (all activations bf16, NHWC) ----------------
__device__ __align__(16) bf g_xh[INLEN*LS];
__device__ __align__(16) bf g_hh[4*LS];
__device__ __align__(16) bf g_mh[LS];
__device__ __align__(16) bf g_memh[GPX*128];
__device__ __align__(16) bf g_oth[TT*LS];
__device__ __align__(16) bf g_xhm[(size_t)GPX*896];     // bf16 pre-activations
__device__ float g_c[4*LS];
__device__ float g_m[LS];
__device__ __align__(16) bf g_W1[(size_t)4*14*18*2048];
__device__ __align__(16) bf g_W2[(size_t)4*36*4096];
__device__ __align__(16) bf g_W3[18*2048];
__device__ float g_b1[4*896], g_b2[4*128];

// ---------------- helpers ----------------
__device__ __forceinline__ uint32_t smem_u32(const void* p) {
    uint32_t a;
    asm("{ .reg .u64 t; cvta.to.shared.u64 t, %1; cvt.u32.u64 %0, t; }" : "=r"(a) : "l"(p));
    return a;
}
__device__ __forceinline__ float sigf(float v) { return 1.0f / (1.0f + expf(-v)); }
__device__ __forceinline__ void cpa16(uint32_t d, const void* s, uint32_t srcsz) {
    asm volatile("cp.async.cg.shared.global [%0], [%1], 16, %2;" :: "r"(d), "l"(s), "r"(srcsz));
}
__device__ __forceinline__ void cpa_commit() { asm volatile("cp.async.commit_group;" ::: "memory"); }
template<int N>
__device__ __forceinline__ void cpa_wait() { asm volatile("cp.async.wait_group %0;" :: "n"(N) : "memory"); }
__device__ __forceinline__ void ldm4(uint32_t* r, uint32_t a) {
    asm volatile("ldmatrix.sync.aligned.m8n8.x4.shared.b16 {%0,%1,%2,%3}, [%4];"
        : "=r"(r[0]), "=r"(r[1]), "=r"(r[2]), "=r"(r[3]) : "r"(a));
}
__device__ __forceinline__ void mma16816(float* d, const uint32_t* a, const uint32_t* b) {
    asm volatile("mma.sync.aligned.m16n8k16.row.col.f32.bf16.bf16.f32 "
        "{%0,%1,%2,%3}, {%4,%5,%6,%7}, {%8,%9}, {%0,%1,%2,%3};"
        : "+f"(d[0]), "+f"(d[1]), "+f"(d[2]), "+f"(d[3])
        : "r"(a[0]), "r"(a[1]), "r"(a[2]), "r"(a[3]), "r"(b[0]), "r"(b[1]));
}
template<int COT>
__device__ __forceinline__ void stageW(const bf* W, uint32_t Wb, int c, int tid) {
    const char* ws = (const char*)(W + (size_t)c * COT * 32);
    const uint32_t wb = Wb + (uint32_t)(c & 1) * (COT * 80);
    for (int i = tid; i < COT * 4; i += 256) {
        const int r = i >> 2, sg = i & 3;
        cpa16(wb + r * 80 + sg * 16, ws + r * 64 + sg * 16, 16);
    }
}

// =====================================================================
// Pure-bf16 implicit-GEMM conv via mma.sync.
// EPI 0: xhm bf16 store (gemm1)  EPI 1: fused gate2  EPI 2: decoder
// =====================================================================
template<int CIW, int COT, int PXT, int EPI>
__global__ void __launch_bounds__(256) gemm_k(
    const bf* __restrict__ xH, const bf* __restrict__ hH, const bf* __restrict__ mH,
    const bf* __restrict__ Wg, const float* __restrict__ bias,
    bf* __restrict__ xhm,
    bf* __restrict__ o0h, bf* __restrict__ o1h,
    float* __restrict__ dec)
{
    constexpr int NCH    = 9 * CIW / 32;
    constexpr int CPT    = CIW / 32;
    constexpr int APITCH = CIW * 2 + 16;
    constexpr int SROWS  = (PXT / 32 + 2) * 34;
    constexpr int APLANE = SROWS * APITCH;
    constexpr int WPLANE = COT * 80;
    constexpr int SEGS   = CIW / 8;
    constexpr int COG    = COT / 32;        // co groups of 32
    constexpr int PPW    = PXT / (8 / COG); // pixels per warp
    constexpr int NF     = PPW / 16;        // 16-px fragments per warp

    extern __shared__ char smem[];
    const int tid = threadIdx.x, wid = tid >> 5, lane = tid & 31;
    const uint32_t sb = smem_u32(smem);
    const uint32_t Wb = sb + APLANE;

    const int mt = blockIdx.y;
    const bf* srcH;
    if (EPI == 0) {
        if (mt < 7)       srcH = xH;
        else if (mt < 11) srcH = hH;
        else              srcH = mH;
    } else srcH = xH;
    const bf* W = Wg + (size_t)mt * NCH * COT * 32;

    const int px0 = blockIdx.x * PXT;
    const int img = px0 >> 10;
    const int y0  = (px0 & 1023) >> 5;

    // ---- stage A (once, halo, zero-filled borders) ----
    for (int i = tid; i < SROWS * SEGS; i += 256) {
        const int s = i / SEGS, seg = i % SEGS;
        const int yy = y0 + s / 34 - 1, xx = s % 34 - 1;
        const bool v = ((unsigned)yy < 32u) && ((unsigned)xx < 32u);
        const size_t off = v ? ((size_t)((img << 10) + yy * 32 + xx) * CIW + seg * 8) * 2 : 0;
        cpa16(sb + (uint32_t)s * APITCH + seg * 16, (const char*)srcH + off, v ? 16u : 0u);
    }
    stageW<COT>(W, Wb, 0, tid);
    cpa_commit();

    // ---- warp geometry ----
    const int wco = wid & (COG - 1);
    const int wpx = wid / COG;
    const int arow = lane & 15, ahalf = lane >> 4;
    const int brow = (lane & 7) + ((lane >> 4) << 3);
    const int bhalf = (lane >> 3) & 1;
    int siteB[NF];
#pragma unroll
    for (int nf = 0; nf < NF; nf++) {
        const int p0 = wpx * PPW + nf * 16;
        siteB[nf] = ((p0 >> 5) + 1) * 34 + (p0 & 31) + brow + 1;
    }

    float acc[2][2 * NF][4] = {};

    for (int c = 0; c < NCH; c++) {
        if (c + 1 < NCH) { stageW<COT>(W, Wb, c + 1, tid); cpa_commit(); cpa_wait<1>(); }
        else             { cpa_wait<0>(); }
        __syncthreads();

        const int tap = c / CPT, ci0 = (c % CPT) * 32;
        const int sh = (tap / 3 - 1) * 34 + (tap % 3 - 1);
        const uint32_t wbase = Wb + (uint32_t)(c & 1) * WPLANE + (uint32_t)(wco * 32) * 80;
        const uint32_t abk = sb + (uint32_t)(ci0 * 2) + (uint32_t)(bhalf * 16);

#pragma unroll
        for (int kf = 0; kf < 2; kf++) {
            uint32_t wh_[2][4];
#pragma unroll
            for (int mf = 0; mf < 2; mf++) {
                const uint32_t ad = wbase + (uint32_t)(mf * 16 + arow) * 80 + kf * 32 + ahalf * 16;
                ldm4(wh_[mf], ad);
            }
#pragma unroll
            for (int nf = 0; nf < NF; nf++) {
                uint32_t bh_[4];
                const uint32_t ad = abk + (uint32_t)(siteB[nf] + sh) * APITCH + kf * 32;
                ldm4(bh_, ad);
#pragma unroll
                for (int mf = 0; mf < 2; mf++)
#pragma unroll
                    for (int j = 0; j < 2; j++)
                        mma16816(acc[mf][nf * 2 + j], wh_[mf], &bh_[j * 2]);
            }
        }
        __syncthreads();
    }
    __syncthreads();

    if (EPI == 0) {
        // transpose to bf16 [px][co] (pitch 72), bias added in fp32
        bf* Dt16 = (bf*)smem;
        const int coG = mt * 64;
#pragma unroll
        for (int mf = 0; mf < 2; mf++) {
            const int row = wco * 32 + mf * 16 + (lane >> 2);
            const float b0 = bias[coG + row], b1v = bias[coG + row + 8];
#pragma unroll
            for (int n4 = 0; n4 < 2 * NF; n4++) {
                const int col = wpx * PPW + n4 * 8 + (lane & 3) * 2;
                Dt16[col * 72 + row]           = __float2bfloat16(acc[mf][n4][0] + b0);
                Dt16[(col + 1) * 72 + row]     = __float2bfloat16(acc[mf][n4][1] + b0);
                Dt16[col * 72 + row + 8]       = __float2bfloat16(acc[mf][n4][2] + b1v);
                Dt16[(col + 1) * 72 + row + 8] = __float2bfloat16(acc[mf][n4][3] + b1v);
            }
        }
        __syncthreads();
        for (int i = tid * 8; i < PXT * 64; i += 2048) {
            const int px = i >> 6, co = i & 63;
            *(uint4*)&xhm[(size_t)(px0 + px) * 896 + coG + co] =
                *(const uint4*)&Dt16[px * 72 + co];
        }
    } else if (EPI == 1) {
        float* Dt = (float*)smem;
#pragma unroll
        for (int mf = 0; mf < 2; mf++)
#pragma unroll
            for (int n4 = 0; n4 < 2 * NF; n4++) {
                const int row = wco * 32 + mf * 16 + (lane >> 2);
                const int col = wpx * PPW + n4 * 8 + (lane & 3) * 2;
                Dt[col * 132 + row]           = acc[mf][n4][0];
                Dt[(col + 1) * 132 + row]     = acc[mf][n4][1];
                Dt[col * 132 + row + 8]       = acc[mf][n4][2];
                Dt[(col + 1) * 132 + row + 8] = acc[mf][n4][3];
            }
        __syncthreads();
        for (int i = tid; i < PXT * 64; i += 256) {
            const int px = i >> 6, ch = i & 63;
            const size_t g = (size_t)(px0 + px);
            const float oc = Dt[px * 132 + ch] + bias[ch];
            const float lc = Dt[px * 132 + 64 + ch] + bias[64 + ch];
            const float ox = __bfloat162float(xhm[g * 896 + 384 + ch]);
            const float oh = __bfloat162float(xhm[g * 896 + 640 + ch]);
            const float ot = sigf(oc + ox + oh);
            const bf hi = __float2bfloat16(ot * tanhf(lc));
            o0h[g * 64 + ch] = hi;
            if (o1h) o1h[g * 64 + ch] = hi;
        }
    } else {
        float* Dt = (float*)smem;
#pragma unroll
        for (int mf = 0; mf < 2; mf++)
#pragma unroll
            for (int n4 = 0; n4 < 2 * NF; n4++) {
                const int row = wco * 32 + mf * 16 + (lane >> 2);
                const int col = wpx * PPW + n4 * 8 + (lane & 3) * 2;
                Dt[col * 68 + row]           = acc[mf][n4][0];
                Dt[(col + 1) * 68 + row]     = acc[mf][n4][1];
                Dt[col * 68 + row + 8]       = acc[mf][n4][2];
                Dt[(col + 1) * 68 + row + 8] = acc[mf][n4][3];
            }
        __syncthreads();
        const int t = px0 >> 13, b = (px0 >> 10) & 7;
        const size_t obase = (size_t)(b * TT + t) * 65536;
        for (int j = tid; j < PXT * 64; j += 256) {
            const int xx = j & 31, yy = (j >> 5) & 3, ch = j >> 7;
            const float v = sigf(Dt[(yy * 32 + xx) * 68 + ch] + bias[ch]);
            dec[obase + (size_t)((ch >> 3) * 32 + y0 + yy) * 256 + (ch & 7) * 32 + xx] = v;
        }
    }
}

// ---------------- gate 1 (reads bf16 xhm) ----------------
__global__ void gate1_k(const bf* __restrict__ xhm, float* __restrict__ c,
                        float* __restrict__ m, bf* __restrict__ memh,
                        bf* __restrict__ mh)
{
    const int idx = blockIdx.x * 256 + threadIdx.x;
    const int px = idx >> 6, ch = idx & 63;
    const bf* v = xhm + (size_t)px * 896;
    const float it  = sigf(__bfloat162float(v[ch])        + __bfloat162float(v[448 + ch]));
    const float ft  = sigf(__bfloat162float(v[64 + ch])   + __bfloat162float(v[512 + ch]));
    const float gt  = tanhf(__bfloat162float(v[128 + ch]) + __bfloat162float(v[576 + ch]));
    const float cn  = ft * c[idx] + it * gt;
    const float itp = sigf(__bfloat162float(v[192 + ch])  + __bfloat162float(v[704 + ch]));
    const float ftp = sigf(__bfloat162float(v[256 + ch])  + __bfloat162float(v[768 + ch]));
    const float gtp = tanhf(__bfloat162float(v[320 + ch]) + __bfloat162float(v[832 + ch]));
    const float mn  = ftp * m[idx] + itp * gtp;
    c[idx] = cn; m[idx] = mn;
    const bf chi = __float2bfloat16(cn);
    const bf mhi = __float2bfloat16(mn);
    memh[(size_t)px * 128 + ch]      = chi;
    memh[(size_t)px * 128 + 64 + ch] = mhi;
    mh[idx] = mhi;
}

// ---------------- patch ----------------
__global__ void patch_k(const float* __restrict__ x, bf* __restrict__ xh)
{
    const int idx = blockIdx.x * 256 + threadIdx.x;
    const int ch = idx & 63, yx = (idx >> 6) & 1023;
    const int b = (idx >> 16) & 7, t = idx >> 19;
    xh[idx] = __float2bfloat16(
        x[(size_t)(b * INLEN + t) * 65536 +
          (size_t)((ch >> 3) * 32 + (yx >> 5)) * 256 + (ch & 7) * 32 + (yx & 31)]);
}

// ---------------- fused zero ----------------
__global__ void zero_all(float4* hh, float4* mh, float4* c, float4* m)
{
    const int i = blockIdx.x * 256 + threadIdx.x;
    const float4 z = make_float4(0.f, 0.f, 0.f, 0.f);
    if (i < 262144)       hh[i] = z;
    else if (i < 327680)  mh[i - 262144] = z;
    else if (i < 851968)  c[i - 327680] = z;
    else                  m[i - 851968] = z;
}

// ---------------- all weight prep fused into one kernel ----------------
__global__ void prep_k(const float* __restrict__ Wx, const float* __restrict__ Wh,
                       const float* __restrict__ Wm, const float* __restrict__ Wo,
                       const float* __restrict__ Wl, const float* __restrict__ Wd,
                       const float* __restrict__ bx, const float* __restrict__ bh,
                       const float* __restrict__ bm, const float* __restrict__ bo,
                       const float* __restrict__ bl,
                       bf* __restrict__ dW1, bf* __restrict__ dW2, bf* __restrict__ dWd,
                       float* __restrict__ b1, float* __restrict__ b2)
{
    const int idx = blockIdx.x * 256 + threadIdx.x;
    if (idx < 2064384) {            // W1: 4l x 14mt x 18c x 2048
        const int kk = idx & 31, row = (idx >> 5) & 63;
        const int c = (idx >> 11) % 18, r2 = (idx >> 11) / 18;
        const int mt = r2 % 14, l = r2 / 14;
        const int co = mt * 64 + row, tap = c >> 1, ci = ((c & 1) << 5) + kk;
        float v;
        if (co < 448)      v = Wx[((size_t)(l * 448 + co) * 64 + ci) * 9 + tap];
        else if (co < 704) v = Wh[((size_t)(l * 256 + co - 448) * 64 + ci) * 9 + tap];
        else               v = Wm[((size_t)(l * 192 + co - 704) * 64 + ci) * 9 + tap];
        dW1[((size_t)(l * 14 + mt) * 18 + c) * 2048 + row * 32 + kk] = __float2bfloat16(v);
    } else if (idx < 2654208) {     // W2: 4l x 36c x 4096
        const int j = idx - 2064384;
        const int kk = j & 31, row = (j >> 5) & 127;
        const int c = (j >> 12) % 36, l = (j >> 12) / 36;
        const int tap = c >> 2, ci = ((c & 3) << 5) + kk;
        float v = 0.f;
        if (row < 64)      v = Wo[((size_t)(l * 64 + row) * 128 + ci) * 9 + tap];
        else if (tap == 4) v = Wl[(size_t)(l * 64 + row - 64) * 128 + ci];
        dW2[((size_t)(l * 36 + c)) * 4096 + row * 32 + kk] = __float2bfloat16(v);
    } else if (idx < 2691072) {     // Wd: 18c x 2048
        const int j = idx - 2654208;
        const int kk = j & 31, row = (j >> 5) & 63, c = j >> 11;
        const int tap = c >> 1, ci = ((c & 1) << 5) + kk;
        dWd[(size_t)c * 2048 + row * 32 + kk] =
            __float2bfloat16(Wd[((size_t)row * 64 + ci) * 9 + tap]);
    } else if (idx < 2694656) {     // b1
        const int j = idx - 2691072;
        const int l = j / 896, q = j % 896;
        b1[j] = q < 448 ? bx[l * 448 + q]
              : q < 704 ? bh[l * 256 + q - 448]
                        : bm[l * 192 + q - 704];
    } else if (idx < 2695168) {     // b2
        const int j = idx - 2694656;
        const int l = j / 128, q = j % 128;
        b2[j] = q < 64 ? bo[l * 64 + q] : bl[l * 64 + q - 64];
    }
}

// =====================================================================
extern "C" void kernel_launch(void* const* d_in, const int* in_sizes, int n_in,
                              void* d_out, int out_size)
{
    const float* x  = (const float*)d_in[0];
    const float* Wx = (const float*)d_in[3];
    const float* bx = (const float*)d_in[4];
    const float* Wh = (const float*)d_in[5];
    const float* bh = (const float*)d_in[6];
    const float* Wm = (const float*)d_in[7];
    const float* bm = (const float*)d_in[8];
    const float* Wo = (const float*)d_in[9];
    const float* bo = (const float*)d_in[10];
    const float* Wl = (const float*)d_in[11];
    const float* bl = (const float*)d_in[12];
    const float* Wd = (const float*)d_in[13];
    const float* bd = (const float*)d_in[14];
    float* out = (float*)d_out;

    bf *xh, *hh, *mh, *memh, *oth, *xhm, *W1, *W2, *W3;
    float *c, *m, *b1, *b2;
    cudaGetSymbolAddress((void**)&xh,   g_xh);
    cudaGetSymbolAddress((void**)&hh,   g_hh);
    cudaGetSymbolAddress((void**)&mh,   g_mh);
    cudaGetSymbolAddress((void**)&memh, g_memh);
    cudaGetSymbolAddress((void**)&oth,  g_oth);
    cudaGetSymbolAddress((void**)&xhm,  g_xhm);
    cudaGetSymbolAddress((void**)&c,    g_c);
    cudaGetSymbolAddress((void**)&m,    g_m);
    cudaGetSymbolAddress((void**)&W1,   g_W1);
    cudaGetSymbolAddress((void**)&W2,   g_W2);
    cudaGetSymbolAddress((void**)&W3,   g_W3);
    cudaGetSymbolAddress((void**)&b1,   g_b1);
    cudaGetSymbolAddress((void**)&b2,   g_b2);

    const int SM1 = 340 * 144 + 2 * 5120;    // gemm1 PXT=256: 59200
    const int SM2 = 136 * 272 + 2 * 10240;   // gemm2: 57472
    const int SM3 = 204 * 144 + 2 * 5120;    // decoder PXT=128: 39616
    cudaFuncSetAttribute(gemm_k<64, 64, 256, 0>,
                         cudaFuncAttributeMaxDynamicSharedMemorySize, SM1);
    cudaFuncSetAttribute(gemm_k<128, 128, 64, 1>,
                         cudaFuncAttributeMaxDynamicSharedMemorySize, SM2);
    cudaFuncSetAttribute(gemm_k<64, 64, 128, 2>,
                         cudaFuncAttributeMaxDynamicSharedMemorySize, SM3);

    zero_all<<<3840, 256>>>((float4*)hh, (float4*)mh, (float4*)c, (float4*)m);
    patch_k<<<20480, 256>>>(x, xh);
    prep_k<<<10528, 256>>>(Wx, Wh, Wm, Wo, Wl, Wd, bx, bh, bm, bo, bl,
                           W1, W2, W3, b1, b2);

    for (int t = 0; t < TT; t++) {
        const bf* curh = (t < INLEN) ? (xh + (size_t)t * LS) : (oth + (size_t)(t - 1) * LS);
        for (int l = 0; l < 4; l++) {
            const bf* inh = (l == 0) ? curh : (hh + (size_t)(l - 1) * LS);
            gemm_k<64, 64, 256, 0><<<dim3(32, 14), 256, SM1>>>(
                inh, hh + (size_t)l * LS, mh,
                W1 + (size_t)l * 14 * 18 * 2048, b1 + l * 896, xhm,
                nullptr, nullptr, nullptr);
            gate1_k<<<2048, 256>>>(xhm, c + (size_t)l * LS, m, memh, mh);
            gemm_k<128, 128, 64, 1><<<dim3(128, 1), 256, SM2>>>(
                memh, nullptr, nullptr,
                W2 + (size_t)l * 36 * 4096, b2 + l * 128, xhm,
                hh + (size_t)l * LS,
                (l == 3) ? (oth + (size_t)t * LS) : nullptr, nullptr);
        }
    }

    gemm_k<64, 64, 128, 2><<<dim3(1216, 1), 256, SM3>>>(
        oth, nullptr, nullptr, W3, bd, nullptr, nullptr, nullptr, out);
}

// round 11
// speedup vs baseline: 1.0951x; 1.0951x over previous
#include <cuda_runtime.h>
#include <cuda_bf16.h>
#include <math.h>
#include <stdint.h>

#define TT    19
#define INLEN 10
#define GPX   8192
#define LS    (GPX*64)
typedef __nv_bfloat16 bf;

// ---------------- device scratch (all activations bf16, NHWC) ----------------
__device__ __align__(16) bf g_xh[INLEN*LS];
__device__ __align__(16) bf g_hh[4*LS];
__device__ __align__(16) bf g_mh[LS];
__device__ __align__(16) bf g_memh[GPX*128];
__device__ __align__(16) bf g_oth[TT*LS];
__device__ __align__(16) bf g_xhm[(size_t)GPX*896];
__device__ float g_c[4*LS];
__device__ float g_m[LS];
__device__ __align__(16) bf g_W1[(size_t)4*14*18*2048];   // packed fragment order
__device__ __align__(16) bf g_W2[(size_t)4*36*4096];
__device__ __align__(16) bf g_W3[18*2048];
__device__ float g_b1[4*896], g_b2[4*128];

// ---------------- helpers ----------------
__device__ __forceinline__ uint32_t smem_u32(const void* p) {
    uint32_t a;
    asm("{ .reg .u64 t; cvta.to.shared.u64 t, %1; cvt.u32.u64 %0, t; }" : "=r"(a) : "l"(p));
    return a;
}
__device__ __forceinline__ float sigf(float v) { return 1.0f / (1.0f + expf(-v)); }
__device__ __forceinline__ void cpa16(uint32_t d, const void* s, uint32_t srcsz) {
    asm volatile("cp.async.cg.shared.global [%0], [%1], 16, %2;" :: "r"(d), "l"(s), "r"(srcsz));
}
__device__ __forceinline__ void cpa_commit() { asm volatile("cp.async.commit_group;" ::: "memory"); }
template<int N>
__device__ __forceinline__ void cpa_wait() { asm volatile("cp.async.wait_group %0;" :: "n"(N) : "memory"); }
__device__ __forceinline__ void ldm4(uint32_t* r, uint32_t a) {
    asm volatile("ldmatrix.sync.aligned.m8n8.x4.shared.b16 {%0,%1,%2,%3}, [%4];"
        : "=r"(r[0]), "=r"(r[1]), "=r"(r[2]), "=r"(r[3]) : "r"(a));
}
__device__ __forceinline__ void mma16816(float* d, const uint32_t* a, const uint32_t* b) {
    asm volatile("mma.sync.aligned.m16n8k16.row.col.f32.bf16.bf16.f32 "
        "{%0,%1,%2,%3}, {%4,%5,%6,%7}, {%8,%9}, {%0,%1,%2,%3};"
        : "+f"(d[0]), "+f"(d[1]), "+f"(d[2]), "+f"(d[3])
        : "r"(a[0]), "r"(a[1]), "r"(a[2]), "r"(a[3]), "r"(b[0]), "r"(b[1]));
}
// stage one packed weight chunk (COT*64 bytes) into ring slot c&3
template<int COT>
__device__ __forceinline__ void stageWc(const bf* W, uint32_t Wb, int c, int tid) {
    const char* ws = (const char*)W + (size_t)c * COT * 64;
    const uint32_t wb = Wb + (uint32_t)(c & 3) * (COT * 64);
    for (int i = tid; i < COT * 4; i += 256)
        cpa16(wb + i * 16, ws + i * 16, 16);
}

// =====================================================================
// Pure-bf16 implicit-GEMM conv via mma.sync.
// Weights in packed ldmatrix-fragment layout (conflict-free, no padding).
// EPI 0: xhm (gemm1, W resident, barrier-free mainloop)
// EPI 1: fused gate2 (gemm2, 4-deep W ring, 1 barrier/chunk)
// EPI 2: decoder (W resident)
// =====================================================================
template<int CIW, int COT, int PXT, int EPI>
__global__ void __launch_bounds__(256) gemm_k(
    const bf* __restrict__ xH, const bf* __restrict__ hH, const bf* __restrict__ mH,
    const bf* __restrict__ Wg, const float* __restrict__ bias,
    bf* __restrict__ xhm,
    bf* __restrict__ o0h, bf* __restrict__ o1h,
    float* __restrict__ dec)
{
    constexpr int NCH    = 9 * CIW / 32;
    constexpr int CPT    = CIW / 32;
    constexpr int APITCH = CIW * 2 + 16;
    constexpr int SROWS  = (PXT / 32 + 2) * 34;
    constexpr int APLANE = SROWS * APITCH;
    constexpr int WCHUNK = COT * 64;          // bytes per packed chunk
    constexpr int SEGS   = CIW / 8;
    constexpr int COG    = COT / 32;
    constexpr int PPW    = PXT / (8 / COG);
    constexpr int NF     = PPW / 16;
    constexpr bool RES   = (EPI != 1);        // resident weights

    extern __shared__ char smem[];
    const int tid = threadIdx.x, wid = tid >> 5, lane = tid & 31;
    const uint32_t sb = smem_u32(smem);
    const uint32_t Wb = sb + APLANE;

    const int mt = blockIdx.y;
    const bf* srcH;
    if (EPI == 0) {
        if (mt < 7)       srcH = xH;
        else if (mt < 11) srcH = hH;
        else              srcH = mH;
    } else srcH = xH;
    const bf* W = Wg + (size_t)mt * NCH * COT * 32;

    const int px0 = blockIdx.x * PXT;
    const int img = px0 >> 10;
    const int y0  = (px0 & 1023) >> 5;

    // ---- stage A (once, halo, zero-filled borders) ----
    for (int i = tid; i < SROWS * SEGS; i += 256) {
        const int s = i / SEGS, seg = i % SEGS;
        const int yy = y0 + s / 34 - 1, xx = s % 34 - 1;
        const bool v = ((unsigned)yy < 32u) && ((unsigned)xx < 32u);
        const size_t off = v ? ((size_t)((img << 10) + yy * 32 + xx) * CIW + seg * 8) * 2 : 0;
        cpa16(sb + (uint32_t)s * APITCH + seg * 16, (const char*)srcH + off, v ? 16u : 0u);
    }
    if (RES) {
        const char* ws = (const char*)W;
        for (int i = tid; i < NCH * WCHUNK / 16; i += 256)
            cpa16(Wb + (uint32_t)i * 16, ws + (size_t)i * 16, 16);
        cpa_commit();
        cpa_wait<0>();
        __syncthreads();
    } else {
        stageWc<COT>(W, Wb, 0, tid); cpa_commit();   // group0: A + chunk0
        stageWc<COT>(W, Wb, 1, tid); cpa_commit();
        stageWc<COT>(W, Wb, 2, tid); cpa_commit();
    }

    // ---- warp geometry ----
    const int wco = wid & (COG - 1);
    const int wpx = wid / COG;
    const int brow = (lane & 7) + ((lane >> 4) << 3);
    const int bhalf = (lane >> 3) & 1;
    int siteB[NF];
#pragma unroll
    for (int nf = 0; nf < NF; nf++) {
        const int p0 = wpx * PPW + nf * 16;
        siteB[nf] = ((p0 >> 5) + 1) * 34 + (p0 & 31) + brow + 1;
    }

    float acc[2][2 * NF][4] = {};

    for (int c = 0; c < NCH; c++) {
        if (!RES) {
            const int rem = NCH - 1 - c;
            if (rem >= 2) cpa_wait<2>();
            else if (rem == 1) cpa_wait<1>();
            else cpa_wait<0>();
            __syncthreads();
            if (c + 3 < NCH) { stageWc<COT>(W, Wb, c + 3, tid); cpa_commit(); }
        }
        const int tap = c / CPT, ci0 = (c % CPT) * 32;
        const int sh = (tap / 3 - 1) * 34 + (tap % 3 - 1);
        // packed W: block = wco*4 + kf*2 + mf, each block 512B, lane*16 within
        const uint32_t wcb = Wb + (uint32_t)(RES ? c : (c & 3)) * WCHUNK
                           + ((uint32_t)wco << 11) + ((uint32_t)lane << 4);
        const uint32_t abk = sb + (uint32_t)(ci0 * 2) + (uint32_t)(bhalf * 16);

#pragma unroll
        for (int kf = 0; kf < 2; kf++) {
            uint32_t wh_[2][4];
#pragma unroll
            for (int mf = 0; mf < 2; mf++)
                ldm4(wh_[mf], wcb + (uint32_t)(kf * 1024 + mf * 512));
#pragma unroll
            for (int nf = 0; nf < NF; nf++) {
                uint32_t bh_[4];
                ldm4(bh_, abk + (uint32_t)(siteB[nf] + sh) * APITCH + kf * 32);
#pragma unroll
                for (int mf = 0; mf < 2; mf++)
#pragma unroll
                    for (int j = 0; j < 2; j++)
                        mma16816(acc[mf][nf * 2 + j], wh_[mf], &bh_[j * 2]);
            }
        }
    }
    __syncthreads();

    if (EPI == 0) {
        bf* Dt16 = (bf*)smem;      // [px][co] pitch 72
        const int coG = mt * 64;
#pragma unroll
        for (int mf = 0; mf < 2; mf++) {
            const int row = wco * 32 + mf * 16 + (lane >> 2);
            const float b0 = bias[coG + row], b1v = bias[coG + row + 8];
#pragma unroll
            for (int n4 = 0; n4 < 2 * NF; n4++) {
                const int col = wpx * PPW + n4 * 8 + (lane & 3) * 2;
                Dt16[col * 72 + row]           = __float2bfloat16(acc[mf][n4][0] + b0);
                Dt16[(col + 1) * 72 + row]     = __float2bfloat16(acc[mf][n4][1] + b0);
                Dt16[col * 72 + row + 8]       = __float2bfloat16(acc[mf][n4][2] + b1v);
                Dt16[(col + 1) * 72 + row + 8] = __float2bfloat16(acc[mf][n4][3] + b1v);
            }
        }
        __syncthreads();
        for (int i = tid * 8; i < PXT * 64; i += 2048) {
            const int px = i >> 6, co = i & 63;
            *(uint4*)&xhm[(size_t)(px0 + px) * 896 + coG + co] =
                *(const uint4*)&Dt16[px * 72 + co];
        }
    } else if (EPI == 1) {
        float* Dt = (float*)smem;  // [px][co] pitch 132
#pragma unroll
        for (int mf = 0; mf < 2; mf++)
#pragma unroll
            for (int n4 = 0; n4 < 2 * NF; n4++) {
                const int row = wco * 32 + mf * 16 + (lane >> 2);
                const int col = wpx * PPW + n4 * 8 + (lane & 3) * 2;
                Dt[col * 132 + row]           = acc[mf][n4][0];
                Dt[(col + 1) * 132 + row]     = acc[mf][n4][1];
                Dt[col * 132 + row + 8]       = acc[mf][n4][2];
                Dt[(col + 1) * 132 + row + 8] = acc[mf][n4][3];
            }
        __syncthreads();
        for (int i = tid; i < PXT * 64; i += 256) {
            const int px = i >> 6, ch = i & 63;
            const size_t g = (size_t)(px0 + px);
            const float oc = Dt[px * 132 + ch] + bias[ch];
            const float lc = Dt[px * 132 + 64 + ch] + bias[64 + ch];
            const float ox = __bfloat162float(xhm[g * 896 + 384 + ch]);
            const float oh = __bfloat162float(xhm[g * 896 + 640 + ch]);
            const float ot = sigf(oc + ox + oh);
            const bf hi = __float2bfloat16(ot * tanhf(lc));
            o0h[g * 64 + ch] = hi;
            if (o1h) o1h[g * 64 + ch] = hi;
        }
    } else {
        float* Dt = (float*)smem;  // [px][co] pitch 68
#pragma unroll
        for (int mf = 0; mf < 2; mf++)
#pragma unroll
            for (int n4 = 0; n4 < 2 * NF; n4++) {
                const int row = wco * 32 + mf * 16 + (lane >> 2);
                const int col = wpx * PPW + n4 * 8 + (lane & 3) * 2;
                Dt[col * 68 + row]           = acc[mf][n4][0];
                Dt[(col + 1) * 68 + row]     = acc[mf][n4][1];
                Dt[col * 68 + row + 8]       = acc[mf][n4][2];
                Dt[(col + 1) * 68 + row + 8] = acc[mf][n4][3];
            }
        __syncthreads();
        const int t = px0 >> 13, b = (px0 >> 10) & 7;
        const size_t obase = (size_t)(b * TT + t) * 65536;
        for (int j = tid; j < PXT * 64; j += 256) {
            const int xx = j & 31, yy = (j >> 5) & 3, ch = j >> 7;
            const float v = sigf(Dt[(yy * 32 + xx) * 68 + ch] + bias[ch]);
            dec[obase + (size_t)((ch >> 3) * 32 + y0 + yy) * 256 + (ch & 7) * 32 + xx] = v;
        }
    }
}

// ---------------- gate 1 (reads bf16 xhm) ----------------
__global__ void gate1_k(const bf* __restrict__ xhm, float* __restrict__ c,
                        float* __restrict__ m, bf* __restrict__ memh,
                        bf* __restrict__ mh)
{
    const int idx = blockIdx.x * 256 + threadIdx.x;
    const int px = idx >> 6, ch = idx & 63;
    const bf* v = xhm + (size_t)px * 896;
    const float it  = sigf(__bfloat162float(v[ch])        + __bfloat162float(v[448 + ch]));
    const float ft  = sigf(__bfloat162float(v[64 + ch])   + __bfloat162float(v[512 + ch]));
    const float gt  = tanhf(__bfloat162float(v[128 + ch]) + __bfloat162float(v[576 + ch]));
    const float cn  = ft * c[idx] + it * gt;
    const float itp = sigf(__bfloat162float(v[192 + ch])  + __bfloat162float(v[704 + ch]));
    const float ftp = sigf(__bfloat162float(v[256 + ch])  + __bfloat162float(v[768 + ch]));
    const float gtp = tanhf(__bfloat162float(v[320 + ch]) + __bfloat162float(v[832 + ch]));
    const float mn  = ftp * m[idx] + itp * gtp;
    c[idx] = cn; m[idx] = mn;
    const bf chi = __float2bfloat16(cn);
    const bf mhi = __float2bfloat16(mn);
    memh[(size_t)px * 128 + ch]      = chi;
    memh[(size_t)px * 128 + 64 + ch] = mhi;
    mh[idx] = mhi;
}

// ---------------- patch ----------------
__global__ void patch_k(const float* __restrict__ x, bf* __restrict__ xh)
{
    const int idx = blockIdx.x * 256 + threadIdx.x;
    const int ch = idx & 63, yx = (idx >> 6) & 1023;
    const int b = (idx >> 16) & 7, t = idx >> 19;
    xh[idx] = __float2bfloat16(
        x[(size_t)(b * INLEN + t) * 65536 +
          (size_t)((ch >> 3) * 32 + (yx >> 5)) * 256 + (ch & 7) * 32 + (yx & 31)]);
}

// ---------------- fused zero ----------------
__global__ void zero_all(float4* hh, float4* mh, float4* c, float4* m)
{
    const int i = blockIdx.x * 256 + threadIdx.x;
    const float4 z = make_float4(0.f, 0.f, 0.f, 0.f);
    if (i < 262144)       hh[i] = z;
    else if (i < 327680)  mh[i - 262144] = z;
    else if (i < 851968)  c[i - 327680] = z;
    else                  m[i - 851968] = z;
}

// ---------------- weight prep: packed ldmatrix-fragment layout ----------------
// block = wco*4 + kf*2 + mf; element = block*256 + lane*8 + j
// row = wco*32 + mf*16 + (lane&15); k = kf*16 + (lane>>4)*8 + j
__global__ void prep_k(const float* __restrict__ Wx, const float* __restrict__ Wh,
                       const float* __restrict__ Wm, const float* __restrict__ Wo,
                       const float* __restrict__ Wl, const float* __restrict__ Wd,
                       const float* __restrict__ bx, const float* __restrict__ bh,
                       const float* __restrict__ bm, const float* __restrict__ bo,
                       const float* __restrict__ bl,
                       bf* __restrict__ dW1, bf* __restrict__ dW2, bf* __restrict__ dWd,
                       float* __restrict__ b1, float* __restrict__ b2)
{
    const int idx = blockIdx.x * 256 + threadIdx.x;
    if (idx < 2064384) {            // W1: 4l x 14mt x 18c x 2048 (COG=2)
        const int j = idx & 7, lane = (idx >> 3) & 31, blk = (idx >> 8) & 7;
        const int c = (idx >> 11) % 18, r2 = (idx >> 11) / 18;
        const int mt = r2 % 14, l = r2 / 14;
        const int mf = blk & 1, kf = (blk >> 1) & 1, wcoq = blk >> 2;
        const int row = wcoq * 32 + mf * 16 + (lane & 15);
        const int k = kf * 16 + (lane >> 4) * 8 + j;
        const int co = mt * 64 + row, tap = c >> 1, ci = ((c & 1) << 5) + k;
        float v;
        if (co < 448)      v = Wx[((size_t)(l * 448 + co) * 64 + ci) * 9 + tap];
        else if (co < 704) v = Wh[((size_t)(l * 256 + co - 448) * 64 + ci) * 9 + tap];
        else               v = Wm[((size_t)(l * 192 + co - 704) * 64 + ci) * 9 + tap];
        dW1[((size_t)(l * 14 + mt) * 18 + c) * 2048 + (idx & 2047)] = __float2bfloat16(v);
    } else if (idx < 2654208) {     // W2: 4l x 36c x 4096 (COG=4)
        const int q = idx - 2064384;
        const int j = q & 7, lane = (q >> 3) & 31, blk = (q >> 8) & 15;
        const int c = (q >> 12) % 36, l = (q >> 12) / 36;
        const int mf = blk & 1, kf = (blk >> 1) & 1, wcoq = blk >> 2;
        const int row = wcoq * 32 + mf * 16 + (lane & 15);
        const int k = kf * 16 + (lane >> 4) * 8 + j;
        const int tap = c >> 2, ci = ((c & 3) << 5) + k;
        float v = 0.f;
        if (row < 64)      v = Wo[((size_t)(l * 64 + row) * 128 + ci) * 9 + tap];
        else if (tap == 4) v = Wl[(size_t)(l * 64 + row - 64) * 128 + ci];
        dW2[(size_t)(l * 36 + c) * 4096 + (q & 4095)] = __float2bfloat16(v);
    } else if (idx < 2691072) {     // Wd: 18c x 2048 (COG=2)
        const int q = idx - 2654208;
        const int j = q & 7, lane = (q >> 3) & 31, blk = (q >> 8) & 7;
        const int c = q >> 11;
        const int mf = blk & 1, kf = (blk >> 1) & 1, wcoq = blk >> 2;
        const int row = wcoq * 32 + mf * 16 + (lane & 15);
        const int k = kf * 16 + (lane >> 4) * 8 + j;
        const int tap = c >> 1, ci = ((c & 1) << 5) + k;
        dWd[(size_t)c * 2048 + (q & 2047)] =
            __float2bfloat16(Wd[((size_t)row * 64 + ci) * 9 + tap]);
    } else if (idx < 2694656) {     // b1
        const int q = idx - 2691072;
        const int l = q / 896, r = q % 896;
        b1[q] = r < 448 ? bx[l * 448 + r]
              : r < 704 ? bh[l * 256 + r - 448]
                        : bm[l * 192 + r - 704];
    } else if (idx < 2695168) {     // b2
        const int q = idx - 2694656;
        const int l = q / 128, r = q % 128;
        b2[q] = r < 64 ? bo[l * 64 + r] : bl[l * 64 + r - 64];
    }
}

// =====================================================================
extern "C" void kernel_launch(void* const* d_in, const int* in_sizes, int n_in,
                              void* d_out, int out_size)
{
    const float* x  = (const float*)d_in[0];
    const float* Wx = (const float*)d_in[3];
    const float* bx = (const float*)d_in[4];
    const float* Wh = (const float*)d_in[5];
    const float* bh = (const float*)d_in[6];
    const float* Wm = (const float*)d_in[7];
    const float* bm = (const float*)d_in[8];
    const float* Wo = (const float*)d_in[9];
    const float* bo = (const float*)d_in[10];
    const float* Wl = (const float*)d_in[11];
    const float* bl = (const float*)d_in[12];
    const float* Wd = (const float*)d_in[13];
    const float* bd = (const float*)d_in[14];
    float* out = (float*)d_out;

    bf *xh, *hh, *mh, *memh, *oth, *xhm, *W1, *W2, *W3;
    float *c, *m, *b1, *b2;
    cudaGetSymbolAddress((void**)&xh,   g_xh);
    cudaGetSymbolAddress((void**)&hh,   g_hh);
    cudaGetSymbolAddress((void**)&mh,   g_mh);
    cudaGetSymbolAddress((void**)&memh, g_memh);
    cudaGetSymbolAddress((void**)&oth,  g_oth);
    cudaGetSymbolAddress((void**)&xhm,  g_xhm);
    cudaGetSymbolAddress((void**)&c,    g_c);
    cudaGetSymbolAddress((void**)&m,    g_m);
    cudaGetSymbolAddress((void**)&W1,   g_W1);
    cudaGetSymbolAddress((void**)&W2,   g_W2);
    cudaGetSymbolAddress((void**)&W3,   g_W3);
    cudaGetSymbolAddress((void**)&b1,   g_b1);
    cudaGetSymbolAddress((void**)&b2,   g_b2);

    const int SM1 = 204 * 144 + 18 * 4096;   // gemm1/dec: A 29376 + W 73728 = 103104
    const int SM2 = 136 * 272 + 4 * 8192;    // gemm2: A 36992 + W ring 32768 = 69760
    cudaFuncSetAttribute(gemm_k<64, 64, 128, 0>,
                         cudaFuncAttributeMaxDynamicSharedMemorySize, SM1);
    cudaFuncSetAttribute(gemm_k<128, 128, 64, 1>,
                         cudaFuncAttributeMaxDynamicSharedMemorySize, SM2);
    cudaFuncSetAttribute(gemm_k<64, 64, 128, 2>,
                         cudaFuncAttributeMaxDynamicSharedMemorySize, SM1);

    zero_all<<<3840, 256>>>((float4*)hh, (float4*)mh, (float4*)c, (float4*)m);
    patch_k<<<20480, 256>>>(x, xh);
    prep_k<<<10528, 256>>>(Wx, Wh, Wm, Wo, Wl, Wd, bx, bh, bm, bo, bl,
                           W1, W2, W3, b1, b2);

    for (int t = 0; t < TT; t++) {
        const bf* curh = (t < INLEN) ? (xh + (size_t)t * LS) : (oth + (size_t)(t - 1) * LS);
        for (int l = 0; l < 4; l++) {
            const bf* inh = (l == 0) ? curh : (hh + (size_t)(l - 1) * LS);
            gemm_k<64, 64, 128, 0><<<dim3(64, 14), 256, SM1>>>(
                inh, hh + (size_t)l * LS, mh,
                W1 + (size_t)l * 14 * 18 * 2048, b1 + l * 896, xhm,
                nullptr, nullptr, nullptr);
            gate1_k<<<2048, 256>>>(xhm, c + (size_t)l * LS, m, memh, mh);
            gemm_k<128, 128, 64, 1><<<dim3(128, 1), 256, SM2>>>(
                memh, nullptr, nullptr,
                W2 + (size_t)l * 36 * 4096, b2 + l * 128, xhm,
                hh + (size_t)l * LS,
                (l == 3) ? (oth + (size_t)t * LS) : nullptr, nullptr);
        }
    }

    gemm_k<64, 64, 128, 2><<<dim3(1216, 1), 256, SM1>>>(
        oth, nullptr, nullptr, W3, bd, nullptr, nullptr, nullptr, out);
}